// round 1
// baseline (speedup 1.0000x reference)
#include <cuda_runtime.h>
#include <cuda_bf16.h>
#include <cstdint>

// DiceLoss: predict [16,4,768,768] f32, target [16,768,768] i32, masks [16,768,768] i32
// out: scalar f32
//
// Strategy: streaming one-pass reduction.
//   - softmax relative to class 0 (e0 == 1): only 3 EX2 + 1 RCP MUFU ops/pixel
//   - per-(n,c) num/den accumulators; onehot terms are predicated scalar adds
//   - kernel1: 1024 blocks (64/image), contiguous float4 slabs, deterministic
//     block reduction into fixed __device__ scratch (no atomics, no zero-init)
//   - kernel2: 64 threads finalize loss = mean_{n,c} (1 - (num+1)/(den+1))

#define NB_PER_N   64
#define N_IMG      16
#define C_CLS      4
#define M_PIX      (768 * 768)          // 589824
#define M_VEC      (M_PIX / 4)          // 147456 float4 per (n,c)
#define VEC_PER_BLK (M_VEC / NB_PER_N)  // 2304
#define ITERS      (VEC_PER_BLK / 256)  // 9
#define GRID1      (N_IMG * NB_PER_N)   // 1024

__device__ float g_scratch[GRID1 * 8];

__device__ __forceinline__ float ex2f(float x) {
    float y;
    asm("ex2.approx.f32 %0, %1;" : "=f"(y) : "f"(x));
    return y;
}
__device__ __forceinline__ float rcpf(float x) {
    float y;
    asm("rcp.approx.f32 %0, %1;" : "=f"(y) : "f"(x));
    return y;
}

__device__ __forceinline__ void px(float x0, float x1, float x2, float x3,
                                   int t, int mk,
                                   float& n0, float& n1, float& n2, float& n3,
                                   float& d0, float& d1, float& d2, float& d3) {
    const float L2E = 1.44269504088896340736f;
    float wf = (mk != 0) ? 1.0f : 0.0f;

    // softmax relative to class 0: e0 = 1 exactly
    float t0 = x0 * L2E;
    float e1 = ex2f(fmaf(x1, L2E, -t0));
    float e2 = ex2f(fmaf(x2, L2E, -t0));
    float e3 = ex2f(fmaf(x3, L2E, -t0));
    float s  = 1.0f + e1 + e2 + e3;
    float r  = rcpf(s);          // sm_c = e_c * r, sm_0 = r

    // den squared-softmax terms, gated by mask (wf)
    float r2w = r * r * wf;
    d0 += r2w;                         // (1 * r)^2 * wf
    d1 = fmaf(e1 * e1, r2w, d1);
    d2 = fmaf(e2 * e2, r2w, d2);
    d3 = fmaf(e3 * e3, r2w, d3);

    // select e_t
    float et = (t == 0) ? 1.0f : ((t == 1) ? e1 : ((t == 2) ? e2 : e3));
    // num contribution at class t: mask on -> sm_t, mask off -> 1
    float av = fmaf(wf * r, et, 1.0f - wf);
    // den onehot contribution at class t: mask on -> 1, mask off -> 2
    float bv = 2.0f - wf;

    if (t == 0)      { n0 += av; d0 += bv; }
    else if (t == 1) { n1 += av; d1 += bv; }
    else if (t == 2) { n2 += av; d2 += bv; }
    else             { n3 += av; d3 += bv; }
}

__global__ void __launch_bounds__(256)
dice_partial(const float* __restrict__ pred,
             const int*   __restrict__ tgt,
             const int*   __restrict__ msk) {
    const int n     = blockIdx.x >> 6;     // / NB_PER_N
    const int chunk = blockIdx.x & (NB_PER_N - 1);

    const float4* __restrict__ p0 = (const float4*)(pred + (size_t)(n * 4 + 0) * M_PIX);
    const float4* __restrict__ p1 = (const float4*)(pred + (size_t)(n * 4 + 1) * M_PIX);
    const float4* __restrict__ p2 = (const float4*)(pred + (size_t)(n * 4 + 2) * M_PIX);
    const float4* __restrict__ p3 = (const float4*)(pred + (size_t)(n * 4 + 3) * M_PIX);
    const int4*   __restrict__ tg = (const int4*)(tgt + (size_t)n * M_PIX);
    const int4*   __restrict__ mg = (const int4*)(msk + (size_t)n * M_PIX);

    const int base = chunk * VEC_PER_BLK + threadIdx.x;

    float n0 = 0.f, n1 = 0.f, n2 = 0.f, n3 = 0.f;
    float d0 = 0.f, d1 = 0.f, d2 = 0.f, d3 = 0.f;

#pragma unroll
    for (int it = 0; it < ITERS; ++it) {
        int i = base + it * 256;
        float4 a = __ldcs(p0 + i);
        float4 b = __ldcs(p1 + i);
        float4 c = __ldcs(p2 + i);
        float4 d = __ldcs(p3 + i);
        int4   t = __ldcs(tg + i);
        int4   m = __ldcs(mg + i);

        px(a.x, b.x, c.x, d.x, t.x, m.x, n0, n1, n2, n3, d0, d1, d2, d3);
        px(a.y, b.y, c.y, d.y, t.y, m.y, n0, n1, n2, n3, d0, d1, d2, d3);
        px(a.z, b.z, c.z, d.z, t.z, m.z, n0, n1, n2, n3, d0, d1, d2, d3);
        px(a.w, b.w, c.w, d.w, t.w, m.w, n0, n1, n2, n3, d0, d1, d2, d3);
    }

    // ---- deterministic block reduction of 8 accumulators ----
    float v[8] = {n0, n1, n2, n3, d0, d1, d2, d3};
#pragma unroll
    for (int k = 0; k < 8; ++k) {
#pragma unroll
        for (int o = 16; o > 0; o >>= 1)
            v[k] += __shfl_xor_sync(0xffffffffu, v[k], o);
    }

    __shared__ float sred[8][8];   // [warp][value]
    int warp = threadIdx.x >> 5;
    int lane = threadIdx.x & 31;
    if (lane == 0) {
#pragma unroll
        for (int k = 0; k < 8; ++k) sred[warp][k] = v[k];
    }
    __syncthreads();

    if (threadIdx.x < 8) {
        float s = 0.f;
#pragma unroll
        for (int w = 0; w < 8; ++w) s += sred[w][threadIdx.x];
        g_scratch[blockIdx.x * 8 + threadIdx.x] = s;
    }
}

__global__ void __launch_bounds__(64)
dice_final(float* __restrict__ out) {
    int tid = threadIdx.x;          // 64 threads, one per (n, c)
    int n = tid >> 2;
    int c = tid & 3;

    float num = 1.0f;   // SMOOTH
    float den = 1.0f;   // SMOOTH
#pragma unroll 4
    for (int b = 0; b < NB_PER_N; ++b) {
        const float* s = g_scratch + (size_t)(n * NB_PER_N + b) * 8;
        num += s[c];
        den += s[4 + c];
    }
    float loss = 1.0f - num / den;

    // reduce 64 values across 2 warps
#pragma unroll
    for (int o = 16; o > 0; o >>= 1)
        loss += __shfl_xor_sync(0xffffffffu, loss, o);

    __shared__ float sh[2];
    if ((tid & 31) == 0) sh[tid >> 5] = loss;
    __syncthreads();
    if (tid == 0)
        out[0] = (sh[0] + sh[1]) * (1.0f / (N_IMG * C_CLS));
}

extern "C" void kernel_launch(void* const* d_in, const int* in_sizes, int n_in,
                              void* d_out, int out_size) {
    const float* pred = (const float*)d_in[0];
    const int*   tgt  = (const int*)d_in[1];
    const int*   msk  = (const int*)d_in[2];
    float*       out  = (float*)d_out;

    dice_partial<<<GRID1, 256>>>(pred, tgt, msk);
    dice_final<<<1, 64>>>(out);
}

// round 3
// speedup vs baseline: 1.0895x; 1.0895x over previous
#include <cuda_runtime.h>
#include <cuda_bf16.h>
#include <cstdint>

// DiceLoss fused single-kernel version.
// predict [16,4,768,768] f32, target [16,768,768] i32, masks [16,768,768] i32 -> scalar f32
//
//   - softmax relative to class 0 (e0 == 1): 3 EX2 + 1 RCP per pixel
//   - 1024 blocks stream contiguous float4 slabs, write 8 partials each to a
//     fixed __device__ scratch slot (deterministic, no zero-init needed)
//   - threadfence-reduction: last block to finish sums all partials, computes
//     the loss, writes d_out, resets the counter (graph-replay safe)
//   - finalize path uses ONLY convergent __syncthreads (all 256 threads)

#define NB_PER_N   64
#define N_IMG      16
#define C_CLS      4
#define M_PIX      (768 * 768)          // 589824
#define M_VEC      (M_PIX / 4)          // 147456 float4 per (n,c)
#define VEC_PER_BLK (M_VEC / NB_PER_N)  // 2304
#define ITERS      (VEC_PER_BLK / 256)  // 9
#define GRID1      (N_IMG * NB_PER_N)   // 1024

__device__ float g_scratch[GRID1 * 8];
__device__ unsigned int g_count = 0;

__device__ __forceinline__ float ex2f(float x) {
    float y;
    asm("ex2.approx.f32 %0, %1;" : "=f"(y) : "f"(x));
    return y;
}
__device__ __forceinline__ float rcpf(float x) {
    float y;
    asm("rcp.approx.f32 %0, %1;" : "=f"(y) : "f"(x));
    return y;
}

__device__ __forceinline__ void px(float x0, float x1, float x2, float x3,
                                   int t, int mk,
                                   float& n0, float& n1, float& n2, float& n3,
                                   float& d0, float& d1, float& d2, float& d3) {
    const float L2E = 1.44269504088896340736f;
    float wf = (mk != 0) ? 1.0f : 0.0f;

    // softmax relative to class 0: e0 = 1 exactly
    float t0 = x0 * L2E;
    float e1 = ex2f(fmaf(x1, L2E, -t0));
    float e2 = ex2f(fmaf(x2, L2E, -t0));
    float e3 = ex2f(fmaf(x3, L2E, -t0));
    float s  = 1.0f + e1 + e2 + e3;
    float r  = rcpf(s);          // sm_c = e_c * r, sm_0 = r

    // den squared-softmax terms, gated by mask (wf)
    float r2w = r * r * wf;
    d0 += r2w;                         // (1 * r)^2 * wf
    d1 = fmaf(e1 * e1, r2w, d1);
    d2 = fmaf(e2 * e2, r2w, d2);
    d3 = fmaf(e3 * e3, r2w, d3);

    // select e_t
    float et = (t == 0) ? 1.0f : ((t == 1) ? e1 : ((t == 2) ? e2 : e3));
    // num contribution at class t: mask on -> sm_t, mask off -> 1
    float av = fmaf(wf * r, et, 1.0f - wf);
    // den onehot contribution at class t: mask on -> 1, mask off -> 2
    float bv = 2.0f - wf;

    if (t == 0)      { n0 += av; d0 += bv; }
    else if (t == 1) { n1 += av; d1 += bv; }
    else if (t == 2) { n2 += av; d2 += bv; }
    else             { n3 += av; d3 += bv; }
}

__global__ void __launch_bounds__(256)
dice_fused(const float* __restrict__ pred,
           const int*   __restrict__ tgt,
           const int*   __restrict__ msk,
           float*       __restrict__ out) {
    const int n     = blockIdx.x >> 6;     // / NB_PER_N
    const int chunk = blockIdx.x & (NB_PER_N - 1);

    const float4* __restrict__ p0 = (const float4*)(pred + (size_t)(n * 4 + 0) * M_PIX);
    const float4* __restrict__ p1 = (const float4*)(pred + (size_t)(n * 4 + 1) * M_PIX);
    const float4* __restrict__ p2 = (const float4*)(pred + (size_t)(n * 4 + 2) * M_PIX);
    const float4* __restrict__ p3 = (const float4*)(pred + (size_t)(n * 4 + 3) * M_PIX);
    const int4*   __restrict__ tg = (const int4*)(tgt + (size_t)n * M_PIX);
    const int4*   __restrict__ mg = (const int4*)(msk + (size_t)n * M_PIX);

    const int base = chunk * VEC_PER_BLK + threadIdx.x;

    float n0 = 0.f, n1 = 0.f, n2 = 0.f, n3 = 0.f;
    float d0 = 0.f, d1 = 0.f, d2 = 0.f, d3 = 0.f;

#pragma unroll
    for (int it = 0; it < ITERS; ++it) {
        int i = base + it * 256;
        float4 a = __ldcs(p0 + i);
        float4 b = __ldcs(p1 + i);
        float4 c = __ldcs(p2 + i);
        float4 d = __ldcs(p3 + i);
        int4   t = __ldcs(tg + i);
        int4   m = __ldcs(mg + i);

        px(a.x, b.x, c.x, d.x, t.x, m.x, n0, n1, n2, n3, d0, d1, d2, d3);
        px(a.y, b.y, c.y, d.y, t.y, m.y, n0, n1, n2, n3, d0, d1, d2, d3);
        px(a.z, b.z, c.z, d.z, t.z, m.z, n0, n1, n2, n3, d0, d1, d2, d3);
        px(a.w, b.w, c.w, d.w, t.w, m.w, n0, n1, n2, n3, d0, d1, d2, d3);
    }

    // ---- deterministic block reduction of 8 accumulators ----
    float v[8] = {n0, n1, n2, n3, d0, d1, d2, d3};
#pragma unroll
    for (int k = 0; k < 8; ++k) {
#pragma unroll
        for (int o = 16; o > 0; o >>= 1)
            v[k] += __shfl_xor_sync(0xffffffffu, v[k], o);
    }

    __shared__ float sred[8][8];   // [warp][value]
    __shared__ bool  s_last;
    int warp = threadIdx.x >> 5;
    int lane = threadIdx.x & 31;
    if (lane == 0) {
#pragma unroll
        for (int k = 0; k < 8; ++k) sred[warp][k] = v[k];
    }
    __syncthreads();

    if (threadIdx.x < 8) {
        float s = 0.f;
#pragma unroll
        for (int w = 0; w < 8; ++w) s += sred[w][threadIdx.x];
        g_scratch[blockIdx.x * 8 + threadIdx.x] = s;
    }

    // ---- completion handshake (release: fence before counter bump) ----
    __threadfence();
    if (threadIdx.x == 0) {
        unsigned int prev = atomicAdd(&g_count, 1u);
        s_last = (prev == GRID1 - 1);
    }
    __syncthreads();
    if (!s_last) return;

    // ================= last block: finalize (all 256 threads alive) ========
    __threadfence();   // acquire: order partial reads after counter observation

    const int tid  = threadIdx.x;
    const int pair = tid >> 2;          // 0..63 -> (n, c)
    const int q    = tid & 3;           // quarter of the 64 chunks
    const int nn   = pair >> 2;
    const int cc   = pair & 3;

    float num = 0.f, den = 0.f;
    const float* sb = g_scratch + ((size_t)(nn * NB_PER_N + q * 16)) * 8;
#pragma unroll
    for (int j = 0; j < 16; ++j) {
        num += __ldcg(sb + j * 8 + cc);
        den += __ldcg(sb + j * 8 + 4 + cc);
    }
    // combine 4 quarters (lanes pair*4 .. pair*4+3 share a warp)
    num += __shfl_xor_sync(0xffffffffu, num, 1);
    den += __shfl_xor_sync(0xffffffffu, den, 1);
    num += __shfl_xor_sync(0xffffffffu, num, 2);
    den += __shfl_xor_sync(0xffffffffu, den, 2);

    __shared__ float s_loss[64];
    if (q == 0)
        s_loss[pair] = 1.0f - (num + 1.0f) / (den + 1.0f);   // SMOOTH = 1
    __syncthreads();   // convergent: executed by all 256 threads

    // warp 0 reduces the 64 losses; no further barrier needed
    if (tid < 32) {
        float l = s_loss[tid] + s_loss[tid + 32];
#pragma unroll
        for (int o = 16; o > 0; o >>= 1)
            l += __shfl_xor_sync(0xffffffffu, l, o);
        if (tid == 0) {
            out[0] = l * (1.0f / (N_IMG * C_CLS));
            g_count = 0;   // reset for next graph replay
        }
    }
}

extern "C" void kernel_launch(void* const* d_in, const int* in_sizes, int n_in,
                              void* d_out, int out_size) {
    const float* pred = (const float*)d_in[0];
    const int*   tgt  = (const int*)d_in[1];
    const int*   msk  = (const int*)d_in[2];
    float*       out  = (float*)d_out;

    dice_fused<<<GRID1, 256>>>(pred, tgt, msk, out);
}